// round 12
// baseline (speedup 1.0000x reference)
#include <cuda_runtime.h>
#include <cuda_bf16.h>
#include <cstdint>

#define BATCH 2
#define CH 64
#define DI 32
#define NP 6400
#define SPL 10
#define QTCH 100               // 64-key chunks per batch (g_Vz stride)
#define TPI 10                 // tiles per item (640 keys)
#define ITEMS 1000             // 2 b * 50 qtiles(128) * 10 splits
#define LOG2E 1.4426950408889634f

// int8 fixed-point scales: q = (12/16384)*(128*qh+ql), k = (9/16384)*(128*kh+kl)
#define S1C 6.591796875e-3f        // (12*9/2^28) * 2^14
#define S2C 5.14984130859375e-5f   // (12*9/2^28) * 2^7

typedef uint32_t u32;
typedef unsigned long long u64;

// ---------------- scratch ----------------
__device__ uint4 g_Qz[BATCH * NP * 4];   // per q row: 4 x 16B {h(4t..),h(16+4t..),l(4t..),l(16+4t..)}
__device__ uint4 g_Kq[BATCH * NP * 4];   // per key row: same format (B-frag compatible)
__device__ uint4 g_Vz[BATCH * DI * QTCH * 16];  // bf16 hi/lo V^T blocks (unchanged)
__device__ float g_thn[BATCH * NP];
__device__ unsigned g_phimax[BATCH];
__device__ unsigned g_ctr;
__device__ float g_acc[BATCH * SPL * NP * DI];
__device__ float g_lp[BATCH * SPL * NP];

// ---------------- helpers ----------------
__device__ __forceinline__ u64 f2fma(u64 a, u64 b, u64 c) {
    u64 d; asm("fma.rn.f32x2 %0,%1,%2,%3;" : "=l"(d) : "l"(a), "l"(b), "l"(c)); return d;
}
__device__ __forceinline__ u64 f2add(u64 a, u64 b) {
    u64 d; asm("add.rn.f32x2 %0,%1,%2;" : "=l"(d) : "l"(a), "l"(b)); return d;
}
__device__ __forceinline__ float f2hadd(u64 a) {
    float lo, hi; asm("mov.b64 {%0,%1},%2;" : "=f"(lo), "=f"(hi) : "l"(a)); return lo + hi;
}
__device__ __forceinline__ u32 pkbf(float hi, float lo) {
    u32 r; asm("cvt.rn.bf16x2.f32 %0,%1,%2;" : "=r"(r) : "f"(hi), "f"(lo)); return r;
}
__device__ __forceinline__ float bflo(u32 p) { return __uint_as_float(p << 16); }
__device__ __forceinline__ float bfhi(u32 p) { return __uint_as_float(p & 0xffff0000u); }
__device__ __forceinline__ float ex2f(float x) {
    float r; asm("ex2.approx.f32 %0,%1;" : "=f"(r) : "f"(x)); return r;
}
__device__ __forceinline__ void mma_bf16(float* c, const u32* a, u32 b0, u32 b1) {
    asm("mma.sync.aligned.m16n8k16.row.col.f32.bf16.bf16.f32 "
        "{%0,%1,%2,%3},{%4,%5,%6,%7},{%8,%9},{%0,%1,%2,%3};"
        : "+f"(c[0]), "+f"(c[1]), "+f"(c[2]), "+f"(c[3])
        : "r"(a[0]), "r"(a[1]), "r"(a[2]), "r"(a[3]), "r"(b0), "r"(b1));
}
__device__ __forceinline__ void mma_s8(int* c, const u32* a, u32 b0, u32 b1) {
    asm("mma.sync.aligned.m16n8k32.row.col.s32.s8.s8.s32 "
        "{%0,%1,%2,%3},{%4,%5,%6,%7},{%8,%9},{%0,%1,%2,%3};"
        : "+r"(c[0]), "+r"(c[1]), "+r"(c[2]), "+r"(c[3])
        : "r"(a[0]), "r"(a[1]), "r"(a[2]), "r"(a[3]), "r"(b0), "r"(b1));
}
__device__ __forceinline__ void cpa16(u32 sa, const void* g) {
    asm volatile("cp.async.cg.shared.global [%0],[%1],16;" :: "r"(sa), "l"(g) : "memory");
}
__device__ __forceinline__ u32 smaddr(const void* p) {
    u32 a; asm("{ .reg .u64 t; cvta.to.shared.u64 t,%1; cvt.u32.u64 %0,t; }" : "=r"(a) : "l"(p));
    return a;
}
__device__ __forceinline__ u32 pk8(const int* q) {
    return (u32)(q[0] & 255) | ((u32)(q[1] & 255) << 8) |
           ((u32)(q[2] & 255) << 16) | ((u32)(q[3] & 255) << 24);
}

// ---------------------------------------------------------------------------
// Stage 1: projection. grid (100, 3, 2), 128 threads; 2 threads per position.
// m=0: theta(*log2e) -> int8 hi/lo g_Qz + thn; m=1: phi -> int8 g_Kq + phimax;
// m=2: g -> bf16 hi/lo transposed g_Vz.
// ---------------------------------------------------------------------------
#define PQ 64
__global__ void __launch_bounds__(128) proj_kernel(
    const float* __restrict__ x,
    const float* __restrict__ theta_w,
    const float* __restrict__ phi_w,
    const float* __restrict__ gw)
{
    __shared__ __align__(16) float xs[CH * PQ];
    __shared__ __align__(16) float wT[CH * DI];

    const int b = blockIdx.z, m = blockIdx.y, n0 = blockIdx.x * PQ;
    const int tid = threadIdx.x;
    const int p = tid >> 1, h = tid & 1;
    const float* wsrc = (m == 0) ? theta_w : (m == 1) ? phi_w : gw;

    for (int idx = tid; idx < DI * CH; idx += 128) {
        int i = idx >> 6, c = idx & 63;
        wT[c * DI + i] = wsrc[idx];
    }
    const float* xb = x + b * CH * NP + n0;
    #pragma unroll
    for (int i = 0; i < 32; i++) {
        int idx = tid + 128 * i;
        xs[idx] = xb[(idx >> 6) * NP + (idx & 63)];
    }
    __syncthreads();

    u64 acc2[8];
    #pragma unroll
    for (int i = 0; i < 8; i++) acc2[i] = 0ull;
    #pragma unroll 4
    for (int c = 0; c < CH; c++) {
        float xv = xs[c * PQ + p];
        u64 x2; asm("mov.b64 %0,{%1,%1};" : "=l"(x2) : "f"(xv));
        const ulonglong2* w2 = (const ulonglong2*)(wT + c * DI + 16 * h);
        #pragma unroll
        for (int i4 = 0; i4 < 4; i4++) {
            ulonglong2 ww = w2[i4];
            acc2[2 * i4]     = f2fma(ww.x, x2, acc2[2 * i4]);
            acc2[2 * i4 + 1] = f2fma(ww.y, x2, acc2[2 * i4 + 1]);
        }
    }
    float v[16];
    #pragma unroll
    for (int i2 = 0; i2 < 8; i2++)
        asm("mov.b64 {%0,%1},%2;" : "=f"(v[2 * i2]), "=f"(v[2 * i2 + 1]) : "l"(acc2[i2]));

    const int n = n0 + p;
    if (m < 2) {
        if (m == 0) {
            #pragma unroll
            for (int i = 0; i < 16; i++) v[i] *= LOG2E;
        }
        const float QI = (m == 0) ? (16384.f / 12.f) : (16384.f / 9.f);
        float nrm = 0.f;
        u32 hw[4], lw[4];
        #pragma unroll
        for (int t = 0; t < 4; t++) {
            int hb[4], lb[4];
            #pragma unroll
            for (int e = 0; e < 4; e++) {
                float f = v[4 * t + e];
                nrm = fmaf(f, f, nrm);
                float tt = f * QI;
                float hf = rintf(tt * 0.0078125f);
                hf = fminf(fmaxf(hf, -127.f), 127.f);
                float lf = rintf(tt - 128.f * hf);
                lf = fminf(fmaxf(lf, -127.f), 127.f);
                hb[e] = (int)hf; lb[e] = (int)lf;
            }
            hw[t] = pk8(hb); lw[t] = pk8(lb);
        }
        nrm += __shfl_xor_sync(0xffffffffu, nrm, 1);
        u32 ohw[4], olw[4];
        #pragma unroll
        for (int t = 0; t < 4; t++) {
            ohw[t] = __shfl_xor_sync(0xffffffffu, hw[t], 1);
            olw[t] = __shfl_xor_sync(0xffffffffu, lw[t], 1);
        }
        uint4* dst = ((m == 0) ? g_Qz : g_Kq) + (b * NP + n) * 4;
        if (h == 0) {
            dst[0] = make_uint4(hw[0], ohw[0], lw[0], olw[0]);
            dst[1] = make_uint4(hw[1], ohw[1], lw[1], olw[1]);
        } else {
            dst[2] = make_uint4(ohw[2], hw[2], olw[2], lw[2]);
            dst[3] = make_uint4(ohw[3], hw[3], olw[3], lw[3]);
        }
        if (m == 0) {
            if (h == 0) g_thn[b * NP + n] = nrm;
        } else {
            unsigned mx = __reduce_max_sync(0xffffffffu, __float_as_uint(nrm));
            if ((tid & 31) == 0) atomicMax(&g_phimax[b], mx);
        }
    } else {
        __syncthreads();       // all xs reads done
        u32* vh = (u32*)xs;    // [32 dims][32 u32-pairs of 64 keys]
        u32* vl = vh + 32 * 32;
        __nv_bfloat16* vhb = (__nv_bfloat16*)vh;
        __nv_bfloat16* vlb = (__nv_bfloat16*)vl;
        #pragma unroll
        for (int i = 0; i < 16; i++) {
            int d = 16 * h + i;
            __nv_bfloat16 hh = __float2bfloat16(v[i]);
            vhb[d * PQ + p] = hh;
            vlb[d * PQ + p] = __float2bfloat16(v[i] - __bfloat162float(hh));
        }
        __syncthreads();
        #pragma unroll
        for (int i = 0; i < 4; i++) {
            int idx = tid + 128 * i;     // 512 blocks
            int d = idx >> 4, rem = idx & 15;
            int s4 = rem >> 2, t4 = rem & 3;
            int kp = 8 * s4 + t4;
            uint4 val = make_uint4(vh[d * 32 + kp], vh[d * 32 + kp + 4],
                                   vl[d * 32 + kp], vl[d * 32 + kp + 4]);
            int blk = ((s4 ^ (d & 1)) << 2) + t4;
            g_Vz[((b * DI + d) * QTCH + blockIdx.x) * 16 + blk] = val;
        }
    }
}

// ---------------------------------------------------------------------------
// Stage 2: persistent flash attention. QK = int8 3-term (24 MMA k32),
// PV = bf16 2-term with l-from-rounded-Ph (32 MMA). 56 slots/warp-tile.
// 296 CTAs x 256 thr. smem: 2 x (K 4KB + V 8KB) + Q 8KB.
// ---------------------------------------------------------------------------
#define KBUF 12288
#define VOFF 4096
#define QOFF 24576
#define SMN  32768
#define ASMEM 32784

__global__ void __launch_bounds__(256, 2) attn_kernel()
{
    extern __shared__ __align__(16) char smem[];
    const int tid = threadIdx.x, w = tid >> 5, lane = tid & 31;
    const int g = lane >> 2, t4 = lane & 3;
    const int gp = g & 1;
    const u32 smbase = smaddr(smem);
    volatile u32* sm_next = (volatile u32*)(smem + SMN);

    auto prefetchKV = [&](int b, int k0, int buf) {
        const u32 bb = smbase + buf * KBUF;
        const uint4* ks = g_Kq + (b * NP + k0) * 4;           // 256 uint4
        const uint4* vs = g_Vz + (b * DI * QTCH + (k0 >> 6)) * 16;
        cpa16(bb + tid * 16, ks + tid);
        #pragma unroll
        for (int i = 0; i < 2; i++) {
            int idx = tid + 256 * i;
            int d = idx >> 4, blk = idx & 15;
            cpa16(bb + VOFF + idx * 16, vs + d * QTCH * 16 + blk);
        }
    };
    auto prefetchQ = [&](int b, int n0) {
        const uint4* qz = g_Qz + (b * NP + n0) * 4;           // 512 uint4
        #pragma unroll
        for (int i = 0; i < 2; i++) {
            int idx = tid + 256 * i;
            cpa16(smbase + QOFF + idx * 16, qz + idx);
        }
    };

    if (tid == 0) *sm_next = atomicAdd(&g_ctr, 1u);
    __syncthreads();
    unsigned wi = *sm_next;
    if (wi < ITEMS) {
        int b = wi / 500, r = wi % 500;
        prefetchKV(b, (r % SPL) * 640, 0);
        prefetchQ(b, (r / SPL) * 128);
        asm volatile("cp.async.commit_group;" ::: "memory");
    }
    int tc = 0;

    while (wi < ITEMS) {
        const int b = wi / 500;
        const int r = wi % 500;
        const int qt = r / SPL, sp = r % SPL;
        const int n0 = qt * 128, k0s = sp * 640;
        const int lr0 = w * 16 + g;
        const int q0 = n0 + lr0, q1 = q0 + 8;

        const float pm = sqrtf(__uint_as_float(g_phimax[b]));
        const float bd0 = sqrtf(g_thn[b * NP + q0]) * pm;
        const float bd1 = sqrtf(g_thn[b * NP + q1]) * pm;

        float o[4][4];
        #pragma unroll
        for (int i = 0; i < 4; i++)
            #pragma unroll
            for (int j = 0; j < 4; j++) o[i][j] = 0.f;
        float l0 = 0.f, l1 = 0.f;
        u32 ah[4], al[4];
        unsigned nwi = ITEMS;

        for (int t = 0; t < TPI; t++) {
            asm volatile("cp.async.wait_group 0;" ::: "memory");
            __syncthreads();

            if (t == 0) {
                // int8 A fragments from Q tile (rows lr0, lr0+8; block t4)
                uint4 u0 = *(const uint4*)(smem + QOFF + lr0 * 64 + t4 * 16);
                uint4 u1 = *(const uint4*)(smem + QOFF + (lr0 + 8) * 64 + t4 * 16);
                ah[0] = u0.x; ah[1] = u1.x; ah[2] = u0.y; ah[3] = u1.y;
                al[0] = u0.z; al[1] = u1.z; al[2] = u0.w; al[3] = u1.w;
            }
            if (t == TPI - 2 && tid == 0) *sm_next = atomicAdd(&g_ctr, 1u);
            if (t < TPI - 1) {
                prefetchKV(b, k0s + (t + 1) * 64, (tc + 1) & 1);
                asm volatile("cp.async.commit_group;" ::: "memory");
            } else {
                nwi = *sm_next;
                if (nwi < ITEMS) {
                    int nb = nwi / 500, nr = nwi % 500;
                    prefetchKV(nb, (nr % SPL) * 640, (tc + 1) & 1);
                    prefetchQ(nb, (nr / SPL) * 128);
                    asm volatile("cp.async.commit_group;" ::: "memory");
                }
            }

            const char* bb = smem + (tc & 1) * KBUF;
            const char* vb0 = bb + VOFF;

            #pragma unroll
            for (int jp = 0; jp < 4; jp++) {
                float p8[8];
                #pragma unroll
                for (int jj = 0; jj < 2; jj++) {
                    const int j = 2 * jp + jj;
                    uint4 kk = *(const uint4*)(bb + ((8 * j + g) << 6) + (t4 << 4));
                    int c1[4] = {0, 0, 0, 0}, c2[4] = {0, 0, 0, 0};
                    mma_s8(c1, ah, kk.x, kk.y);   // qh*kh
                    mma_s8(c2, ah, kk.z, kk.w);   // qh*kl
                    mma_s8(c2, al, kk.x, kk.y);   // ql*kh
                    p8[4 * jj + 0] = ex2f(fmaf((float)c1[0], S1C, fmaf((float)c2[0], S2C, -bd0)));
                    p8[4 * jj + 1] = ex2f(fmaf((float)c1[1], S1C, fmaf((float)c2[1], S2C, -bd0)));
                    p8[4 * jj + 2] = ex2f(fmaf((float)c1[2], S1C, fmaf((float)c2[2], S2C, -bd1)));
                    p8[4 * jj + 3] = ex2f(fmaf((float)c1[3], S1C, fmaf((float)c2[3], S2C, -bd1)));
                }
                u32 ph[4];
                ph[0] = pkbf(p8[1], p8[0]); ph[1] = pkbf(p8[3], p8[2]);
                ph[2] = pkbf(p8[5], p8[4]); ph[3] = pkbf(p8[7], p8[6]);
                // l from the ROUNDED Ph so normalization cancels rounding
                l0 += bflo(ph[0]) + bfhi(ph[0]) + bflo(ph[2]) + bfhi(ph[2]);
                l1 += bflo(ph[1]) + bfhi(ph[1]) + bflo(ph[3]) + bfhi(ph[3]);

                const int so4 = (((jp ^ gp) << 2) + t4) << 4;
                #pragma unroll
                for (int j2 = 0; j2 < 4; j2++) {
                    uint4 vv = *(const uint4*)(vb0 + ((8 * j2 + g) << 8) + so4);
                    mma_bf16(o[j2], ph, vv.x, vv.y);   // Ph * Vh
                    mma_bf16(o[j2], ph, vv.z, vv.w);   // Ph * Vl
                }
            }
            tc++;
        }

        l0 += __shfl_xor_sync(0xffffffffu, l0, 1);
        l0 += __shfl_xor_sync(0xffffffffu, l0, 2);
        l1 += __shfl_xor_sync(0xffffffffu, l1, 1);
        l1 += __shfl_xor_sync(0xffffffffu, l1, 2);

        const int pb = (b * SPL + sp) * NP;
        #pragma unroll
        for (int j2 = 0; j2 < 4; j2++) {
            *(float2*)(g_acc + (pb + q0) * DI + 8 * j2 + 2 * t4) = make_float2(o[j2][0], o[j2][1]);
            *(float2*)(g_acc + (pb + q1) * DI + 8 * j2 + 2 * t4) = make_float2(o[j2][2], o[j2][3]);
        }
        if (t4 == 0) { g_lp[pb + q0] = l0; g_lp[pb + q1] = l1; }

        wi = nwi;
    }
}

// ---------------------------------------------------------------------------
// Stage 3: merge SPL partials + output projection + residual.
// ---------------------------------------------------------------------------
__global__ void __launch_bounds__(128) merge_kernel(
    const float* __restrict__ x,
    const float* __restrict__ w_w,
    float* __restrict__ out)
{
    __shared__ __align__(16) float ws[CH * DI];
    const int b = blockIdx.y, tid = threadIdx.x;
    const int n = blockIdx.x * 128 + tid;

    for (int i = tid; i < CH * DI; i += 128) ws[i] = w_w[i];
    __syncthreads();

    float l = 0.f;
    u64 y2[16];
    #pragma unroll
    for (int i = 0; i < 16; i++) y2[i] = 0ull;
    #pragma unroll 2
    for (int s = 0; s < SPL; s++) {
        l += g_lp[(b * SPL + s) * NP + n];
        const u64* ap = (const u64*)(g_acc + ((b * SPL + s) * NP + n) * DI);
        #pragma unroll
        for (int i2 = 0; i2 < 16; i2++) y2[i2] = f2add(y2[i2], ap[i2]);
    }
    const float inv = 1.f / l;
    u64 inv2; asm("mov.b64 %0,{%1,%1};" : "=l"(inv2) : "f"(inv));
    #pragma unroll
    for (int i2 = 0; i2 < 16; i2++) {
        u64 z = 0ull;
        y2[i2] = f2fma(y2[i2], inv2, z);
    }

    const float* xb = x + b * CH * NP + n;
    float* ob = out + b * CH * NP + n;
    #pragma unroll 2
    for (int c = 0; c < CH; c++) {
        const u64* w2 = (const u64*)(ws + c * DI);
        u64 o2 = 0ull;
        #pragma unroll
        for (int i2 = 0; i2 < 16; i2++) o2 = f2fma(w2[i2], y2[i2], o2);
        ob[c * NP] = xb[c * NP] + f2hadd(o2);
    }
}

// ---------------------------------------------------------------------------
extern "C" void kernel_launch(void* const* d_in, const int* in_sizes, int n_in,
                              void* d_out, int out_size)
{
    const float* x       = (const float*)d_in[0];
    const float* gw      = (const float*)d_in[1];
    const float* theta_w = (const float*)d_in[2];
    const float* phi_w   = (const float*)d_in[3];
    const float* w_w     = (const float*)d_in[4];
    float* out           = (float*)d_out;

    void* pm = nullptr; cudaGetSymbolAddress(&pm, g_phimax);
    cudaMemsetAsync(pm, 0, sizeof(unsigned) * BATCH);
    void* pc = nullptr; cudaGetSymbolAddress(&pc, g_ctr);
    cudaMemsetAsync(pc, 0, sizeof(unsigned));

    static int cfg = 0;
    if (!cfg) {
        cudaFuncSetAttribute(attn_kernel, cudaFuncAttributeMaxDynamicSharedMemorySize, ASMEM);
        cfg = 1;
    }

    dim3 gp(NP / PQ, 3, BATCH);
    proj_kernel<<<gp, 128>>>(x, theta_w, phi_w, gw);

    attn_kernel<<<296, 256, ASMEM>>>();

    dim3 gm(NP / 128, BATCH);
    merge_kernel<<<gm, 128>>>(x, w_w, out);
}

// round 13
// speedup vs baseline: 1.9824x; 1.9824x over previous
#include <cuda_runtime.h>
#include <cuda_bf16.h>
#include <cuda_fp16.h>
#include <cstdint>

#define BATCH 2
#define CH 64
#define DI 32
#define NP 6400
#define SPL 10
#define QTCH 100               // 64-key chunks per batch (g_Vz stride)
#define TPI 10                 // tiles per item (640 keys)
#define ITEMS 1000             // 2 b * 50 qtiles(128) * 10 splits
#define LOG2E 1.4426950408889634f

typedef uint32_t u32;
typedef unsigned long long u64;

// ---------------- scratch ----------------
__device__ uint4 g_Qh[BATCH * NP * 4];   // fp16 q hi: row = 4 uint4 (16 u32 pairs)
__device__ uint4 g_Ql[BATCH * NP * 4];   // fp16 q lo residual
__device__ uint4 g_Kz[BATCH * NP * 4];   // fp16 k single: per key 4 x 16B blocks {b0s0,b1s0,b0s1,b1s1}
__device__ uint4 g_Vz[BATCH * DI * QTCH * 16];  // bf16 hi/lo V^T blocks (unchanged)
__device__ float g_thn[BATCH * NP];
__device__ unsigned g_phimax[BATCH];
__device__ unsigned g_ctr;
__device__ float g_acc[BATCH * SPL * NP * DI];
__device__ float g_lp[BATCH * SPL * NP];

// ---------------- helpers ----------------
__device__ __forceinline__ u64 f2fma(u64 a, u64 b, u64 c) {
    u64 d; asm("fma.rn.f32x2 %0,%1,%2,%3;" : "=l"(d) : "l"(a), "l"(b), "l"(c)); return d;
}
__device__ __forceinline__ u64 f2add(u64 a, u64 b) {
    u64 d; asm("add.rn.f32x2 %0,%1,%2;" : "=l"(d) : "l"(a), "l"(b)); return d;
}
__device__ __forceinline__ float f2hadd(u64 a) {
    float lo, hi; asm("mov.b64 {%0,%1},%2;" : "=f"(lo), "=f"(hi) : "l"(a)); return lo + hi;
}
__device__ __forceinline__ u32 pkbf(float hi, float lo) {
    u32 r; asm("cvt.rn.bf16x2.f32 %0,%1,%2;" : "=r"(r) : "f"(hi), "f"(lo)); return r;
}
__device__ __forceinline__ u32 pkf16(float hi, float lo) {
    u32 r; asm("cvt.rn.f16x2.f32 %0,%1,%2;" : "=r"(r) : "f"(hi), "f"(lo)); return r;
}
__device__ __forceinline__ float f16lo(u32 p) {
    __half_raw hr; hr.x = (unsigned short)(p & 0xffffu); return __half2float(__half(hr));
}
__device__ __forceinline__ float f16hi(u32 p) {
    __half_raw hr; hr.x = (unsigned short)(p >> 16); return __half2float(__half(hr));
}
__device__ __forceinline__ float bflo(u32 p) { return __uint_as_float(p << 16); }
__device__ __forceinline__ float bfhi(u32 p) { return __uint_as_float(p & 0xffff0000u); }
__device__ __forceinline__ float ex2f(float x) {
    float r; asm("ex2.approx.f32 %0,%1;" : "=f"(r) : "f"(x)); return r;
}
__device__ __forceinline__ void mma_bf16(float* c, const u32* a, u32 b0, u32 b1) {
    asm("mma.sync.aligned.m16n8k16.row.col.f32.bf16.bf16.f32 "
        "{%0,%1,%2,%3},{%4,%5,%6,%7},{%8,%9},{%0,%1,%2,%3};"
        : "+f"(c[0]), "+f"(c[1]), "+f"(c[2]), "+f"(c[3])
        : "r"(a[0]), "r"(a[1]), "r"(a[2]), "r"(a[3]), "r"(b0), "r"(b1));
}
__device__ __forceinline__ void mma_f16(float* c, const u32* a, u32 b0, u32 b1) {
    asm("mma.sync.aligned.m16n8k16.row.col.f32.f16.f16.f32 "
        "{%0,%1,%2,%3},{%4,%5,%6,%7},{%8,%9},{%0,%1,%2,%3};"
        : "+f"(c[0]), "+f"(c[1]), "+f"(c[2]), "+f"(c[3])
        : "r"(a[0]), "r"(a[1]), "r"(a[2]), "r"(a[3]), "r"(b0), "r"(b1));
}
__device__ __forceinline__ void cpa16(u32 sa, const void* g) {
    asm volatile("cp.async.cg.shared.global [%0],[%1],16;" :: "r"(sa), "l"(g) : "memory");
}
__device__ __forceinline__ u32 smaddr(const void* p) {
    u32 a; asm("{ .reg .u64 t; cvta.to.shared.u64 t,%1; cvt.u32.u64 %0,t; }" : "=r"(a) : "l"(p));
    return a;
}

// ---------------------------------------------------------------------------
// Stage 1: projection. grid (100, 3, 2), 128 threads; 2 threads per position
// (h = tid&1 owns dims 16h..16h+15), 64 positions per CTA.
// m=0: theta(*log2e) -> fp16 hi/lo g_Qh/g_Ql + thn
// m=1: phi -> fp16 single g_Kz (t4-blocked) + phimax
// m=2: g -> bf16 hi/lo transposed g_Vz
// ---------------------------------------------------------------------------
#define PQ 64
__global__ void __launch_bounds__(128) proj_kernel(
    const float* __restrict__ x,
    const float* __restrict__ theta_w,
    const float* __restrict__ phi_w,
    const float* __restrict__ gw)
{
    __shared__ __align__(16) float xs[CH * PQ];
    __shared__ __align__(16) float wT[CH * DI];

    const int b = blockIdx.z, m = blockIdx.y, n0 = blockIdx.x * PQ;
    const int tid = threadIdx.x;
    const int p = tid >> 1, h = tid & 1;
    const float* wsrc = (m == 0) ? theta_w : (m == 1) ? phi_w : gw;

    for (int idx = tid; idx < DI * CH; idx += 128) {
        int i = idx >> 6, c = idx & 63;
        wT[c * DI + i] = wsrc[idx];
    }
    const float* xb = x + b * CH * NP + n0;
    #pragma unroll
    for (int i = 0; i < 32; i++) {
        int idx = tid + 128 * i;
        xs[idx] = xb[(idx >> 6) * NP + (idx & 63)];
    }
    __syncthreads();

    u64 acc2[8];
    #pragma unroll
    for (int i = 0; i < 8; i++) acc2[i] = 0ull;
    #pragma unroll 4
    for (int c = 0; c < CH; c++) {
        float xv = xs[c * PQ + p];
        u64 x2; asm("mov.b64 %0,{%1,%1};" : "=l"(x2) : "f"(xv));
        const ulonglong2* w2 = (const ulonglong2*)(wT + c * DI + 16 * h);
        #pragma unroll
        for (int i4 = 0; i4 < 4; i4++) {
            ulonglong2 ww = w2[i4];
            acc2[2 * i4]     = f2fma(ww.x, x2, acc2[2 * i4]);
            acc2[2 * i4 + 1] = f2fma(ww.y, x2, acc2[2 * i4 + 1]);
        }
    }
    float v[16];
    #pragma unroll
    for (int i2 = 0; i2 < 8; i2++)
        asm("mov.b64 {%0,%1},%2;" : "=f"(v[2 * i2]), "=f"(v[2 * i2 + 1]) : "l"(acc2[i2]));

    const int n = n0 + p;
    if (m == 0) {
        #pragma unroll
        for (int i = 0; i < 16; i++) v[i] *= LOG2E;
        float nrm = 0.f;
        u32 hw[8], lw[8];
        #pragma unroll
        for (int i2 = 0; i2 < 8; i2++) {
            float f0 = v[2 * i2], f1 = v[2 * i2 + 1];
            nrm = fmaf(f0, f0, fmaf(f1, f1, nrm));
            u32 hh = pkf16(f1, f0);
            hw[i2] = hh;
            lw[i2] = pkf16(f1 - f16hi(hh), f0 - f16lo(hh));
        }
        nrm += __shfl_xor_sync(0xffffffffu, nrm, 1);
        uint4* hp = g_Qh + (b * NP + n) * 4 + 2 * h;
        uint4* lp = g_Ql + (b * NP + n) * 4 + 2 * h;
        hp[0] = make_uint4(hw[0], hw[1], hw[2], hw[3]);
        hp[1] = make_uint4(hw[4], hw[5], hw[6], hw[7]);
        lp[0] = make_uint4(lw[0], lw[1], lw[2], lw[3]);
        lp[1] = make_uint4(lw[4], lw[5], lw[6], lw[7]);
        if (h == 0) g_thn[b * NP + n] = nrm;
    } else if (m == 1) {
        float nrm = 0.f;
        u32 kw[8];
        #pragma unroll
        for (int i2 = 0; i2 < 8; i2++) {
            float f0 = v[2 * i2], f1 = v[2 * i2 + 1];
            nrm = fmaf(f0, f0, fmaf(f1, f1, nrm));
            kw[i2] = pkf16(f1, f0);
        }
        nrm += __shfl_xor_sync(0xffffffffu, nrm, 1);
        u32 ok[8];
        #pragma unroll
        for (int t = 0; t < 8; t++)
            ok[t] = __shfl_xor_sync(0xffffffffu, kw[t], 1);
        // blk[t4] = {u32 idx t4, t4+4, t4+8, t4+12}; h=0 owns idx 0..7, h=1 owns 8..15
        uint4* dst = g_Kz + (b * NP + n) * 4;
        if (h == 0) {
            dst[0] = make_uint4(kw[0], kw[4], ok[0], ok[4]);
            dst[1] = make_uint4(kw[1], kw[5], ok[1], ok[5]);
        } else {
            dst[2] = make_uint4(ok[2], ok[6], kw[2], kw[6]);
            dst[3] = make_uint4(ok[3], ok[7], kw[3], kw[7]);
        }
        unsigned mx = __reduce_max_sync(0xffffffffu, __float_as_uint(nrm));
        if ((tid & 31) == 0) atomicMax(&g_phimax[b], mx);
    } else {
        __syncthreads();       // all xs reads done
        u32* vh = (u32*)xs;    // [32 dims][32 u32-pairs of 64 keys]
        u32* vl = vh + 32 * 32;
        __nv_bfloat16* vhb = (__nv_bfloat16*)vh;
        __nv_bfloat16* vlb = (__nv_bfloat16*)vl;
        #pragma unroll
        for (int i = 0; i < 16; i++) {
            int d = 16 * h + i;
            __nv_bfloat16 hh = __float2bfloat16(v[i]);
            vhb[d * PQ + p] = hh;
            vlb[d * PQ + p] = __float2bfloat16(v[i] - __bfloat162float(hh));
        }
        __syncthreads();
        #pragma unroll
        for (int i = 0; i < 4; i++) {
            int idx = tid + 128 * i;     // 512 blocks
            int d = idx >> 4, rem = idx & 15;
            int s4 = rem >> 2, t4 = rem & 3;
            int kp = 8 * s4 + t4;
            uint4 val = make_uint4(vh[d * 32 + kp], vh[d * 32 + kp + 4],
                                   vl[d * 32 + kp], vl[d * 32 + kp + 4]);
            int blk = ((s4 ^ (d & 1)) << 2) + t4;
            g_Vz[((b * DI + d) * QTCH + blockIdx.x) * 16 + blk] = val;
        }
    }
}

// ---------------------------------------------------------------------------
// Stage 2: persistent flash attention. QK = fp16 2-term (qh,ql x kh) = 32 MMA,
// PV = bf16 2-term with l-from-rounded-Ph = 32 MMA. 64 slots/warp-tile.
// 296 CTAs x 256 thr. smem: 2 x (K 4KB + V 8KB) + Q 16KB.
// ---------------------------------------------------------------------------
#define KBUF 12288
#define VOFF 4096
#define QOFF 24576
#define SMN  40960
#define ASMEM 40976

__global__ void __launch_bounds__(256, 2) attn_kernel()
{
    extern __shared__ __align__(16) char smem[];
    const int tid = threadIdx.x, w = tid >> 5, lane = tid & 31;
    const int g = lane >> 2, t4 = lane & 3;
    const int gp = g & 1;
    const u32 smbase = smaddr(smem);
    volatile u32* sm_next = (volatile u32*)(smem + SMN);

    auto prefetchKV = [&](int b, int k0, int buf) {
        const u32 bb = smbase + buf * KBUF;
        const uint4* ks = g_Kz + (b * NP + k0) * 4;           // 256 uint4
        const uint4* vs = g_Vz + (b * DI * QTCH + (k0 >> 6)) * 16;
        cpa16(bb + tid * 16, ks + tid);
        #pragma unroll
        for (int i = 0; i < 2; i++) {
            int idx = tid + 256 * i;
            int d = idx >> 4, blk = idx & 15;
            cpa16(bb + VOFF + idx * 16, vs + d * QTCH * 16 + blk);
        }
    };
    auto prefetchQ = [&](int b, int n0) {
        const uint4* qh = g_Qh + (b * NP + n0) * 4;           // 512 uint4
        const uint4* ql = g_Ql + (b * NP + n0) * 4;
        #pragma unroll
        for (int i = 0; i < 2; i++) {
            int idx = tid + 256 * i;
            cpa16(smbase + QOFF + idx * 16, qh + idx);
            cpa16(smbase + QOFF + 8192 + idx * 16, ql + idx);
        }
    };

    if (tid == 0) *sm_next = atomicAdd(&g_ctr, 1u);
    __syncthreads();
    unsigned wi = *sm_next;
    if (wi < ITEMS) {
        int b = wi / 500, r = wi % 500;
        prefetchKV(b, (r % SPL) * 640, 0);
        prefetchQ(b, (r / SPL) * 128);
        asm volatile("cp.async.commit_group;" ::: "memory");
    }
    int tc = 0;

    while (wi < ITEMS) {
        const int b = wi / 500;
        const int r = wi % 500;
        const int qt = r / SPL, sp = r % SPL;
        const int n0 = qt * 128, k0s = sp * 640;
        const int lr0 = w * 16 + g;
        const int q0 = n0 + lr0, q1 = q0 + 8;

        const float pm = sqrtf(__uint_as_float(g_phimax[b]));
        const float bd0 = sqrtf(g_thn[b * NP + q0]) * pm;
        const float bd1 = sqrtf(g_thn[b * NP + q1]) * pm;

        float o[4][4];
        #pragma unroll
        for (int i = 0; i < 4; i++)
            #pragma unroll
            for (int j = 0; j < 4; j++) o[i][j] = 0.f;
        float l0 = 0.f, l1 = 0.f;
        u32 ah[2][4], al[2][4];
        unsigned nwi = ITEMS;

        for (int t = 0; t < TPI; t++) {
            asm volatile("cp.async.wait_group 0;" ::: "memory");
            __syncthreads();

            if (t == 0) {
                const u32* qh32 = (const u32*)(smem + QOFF);
                const u32* ql32 = (const u32*)(smem + QOFF + 8192);
                const int r0 = lr0 * 16, r1 = (lr0 + 8) * 16;
                #pragma unroll
                for (int s = 0; s < 2; s++) {
                    ah[s][0] = qh32[r0 + t4 + 8 * s];
                    ah[s][1] = qh32[r1 + t4 + 8 * s];
                    ah[s][2] = qh32[r0 + t4 + 4 + 8 * s];
                    ah[s][3] = qh32[r1 + t4 + 4 + 8 * s];
                    al[s][0] = ql32[r0 + t4 + 8 * s];
                    al[s][1] = ql32[r1 + t4 + 8 * s];
                    al[s][2] = ql32[r0 + t4 + 4 + 8 * s];
                    al[s][3] = ql32[r1 + t4 + 4 + 8 * s];
                }
            }
            if (t == TPI - 2 && tid == 0) *sm_next = atomicAdd(&g_ctr, 1u);
            if (t < TPI - 1) {
                prefetchKV(b, k0s + (t + 1) * 64, (tc + 1) & 1);
                asm volatile("cp.async.commit_group;" ::: "memory");
            } else {
                nwi = *sm_next;
                if (nwi < ITEMS) {
                    int nb = nwi / 500, nr = nwi % 500;
                    prefetchKV(nb, (nr % SPL) * 640, (tc + 1) & 1);
                    prefetchQ(nb, (nr / SPL) * 128);
                    asm volatile("cp.async.commit_group;" ::: "memory");
                }
            }

            const char* bb = smem + (tc & 1) * KBUF;
            const char* vb0 = bb + VOFF;

            // ---- j-pair pipeline: QK(jp+1) | exp/pack(jp) | PV(jp) ----
            float sc[2][2][4];
            u32 ph[4];

            // QK for pair jp: fp16 2-term, acc pre-init to -bound
            #define QK_PAIR(jp, scp)                                            \
                do {                                                            \
                    (scp)[0][0] = -bd0; (scp)[0][1] = -bd0;                     \
                    (scp)[0][2] = -bd1; (scp)[0][3] = -bd1;                     \
                    (scp)[1][0] = -bd0; (scp)[1][1] = -bd0;                     \
                    (scp)[1][2] = -bd1; (scp)[1][3] = -bd1;                     \
                    _Pragma("unroll")                                           \
                    for (int jj = 0; jj < 2; jj++) {                            \
                        int j = 2 * (jp) + jj;                                  \
                        uint4 kk = *(const uint4*)(bb + ((8 * j + g) << 6) + (t4 << 4)); \
                        mma_f16((scp)[jj], ah[0], kk.x, kk.y);                  \
                        mma_f16((scp)[jj], al[0], kk.x, kk.y);                  \
                        mma_f16((scp)[jj], ah[1], kk.z, kk.w);                  \
                        mma_f16((scp)[jj], al[1], kk.z, kk.w);                  \
                    }                                                           \
                } while (0)

            QK_PAIR(0, sc[0]);
            #pragma unroll
            for (int jp = 0; jp < 4; jp++) {
                if (jp < 3) QK_PAIR(jp + 1, sc[(jp + 1) & 1]);

                float* s0 = sc[jp & 1][0];
                float* s1 = sc[jp & 1][1];
                float p0 = ex2f(s0[0]), p1 = ex2f(s0[1]);
                float p2 = ex2f(s0[2]), p3 = ex2f(s0[3]);
                float p4 = ex2f(s1[0]), p5 = ex2f(s1[1]);
                float p6 = ex2f(s1[2]), p7 = ex2f(s1[3]);
                ph[0] = pkbf(p1, p0); ph[1] = pkbf(p3, p2);
                ph[2] = pkbf(p5, p4); ph[3] = pkbf(p7, p6);
                // l from the ROUNDED Ph so normalization cancels rounding
                l0 += bflo(ph[0]) + bfhi(ph[0]) + bflo(ph[2]) + bfhi(ph[2]);
                l1 += bflo(ph[1]) + bfhi(ph[1]) + bflo(ph[3]) + bfhi(ph[3]);

                const int so4 = (((jp ^ gp) << 2) + t4) << 4;
                #pragma unroll
                for (int j2 = 0; j2 < 4; j2++) {
                    uint4 vv = *(const uint4*)(vb0 + ((8 * j2 + g) << 8) + so4);
                    mma_bf16(o[j2], ph, vv.x, vv.y);   // Ph * Vh
                    mma_bf16(o[j2], ph, vv.z, vv.w);   // Ph * Vl
                }
            }
            #undef QK_PAIR
            tc++;
        }

        l0 += __shfl_xor_sync(0xffffffffu, l0, 1);
        l0 += __shfl_xor_sync(0xffffffffu, l0, 2);
        l1 += __shfl_xor_sync(0xffffffffu, l1, 1);
        l1 += __shfl_xor_sync(0xffffffffu, l1, 2);

        const int pb = (b * SPL + sp) * NP;
        #pragma unroll
        for (int j2 = 0; j2 < 4; j2++) {
            *(float2*)(g_acc + (pb + q0) * DI + 8 * j2 + 2 * t4) = make_float2(o[j2][0], o[j2][1]);
            *(float2*)(g_acc + (pb + q1) * DI + 8 * j2 + 2 * t4) = make_float2(o[j2][2], o[j2][3]);
        }
        if (t4 == 0) { g_lp[pb + q0] = l0; g_lp[pb + q1] = l1; }

        wi = nwi;
    }
}

// ---------------------------------------------------------------------------
// Stage 3: merge SPL partials + output projection + residual.
// ---------------------------------------------------------------------------
__global__ void __launch_bounds__(128) merge_kernel(
    const float* __restrict__ x,
    const float* __restrict__ w_w,
    float* __restrict__ out)
{
    __shared__ __align__(16) float ws[CH * DI];
    const int b = blockIdx.y, tid = threadIdx.x;
    const int n = blockIdx.x * 128 + tid;

    for (int i = tid; i < CH * DI; i += 128) ws[i] = w_w[i];
    __syncthreads();

    float l = 0.f;
    u64 y2[16];
    #pragma unroll
    for (int i = 0; i < 16; i++) y2[i] = 0ull;
    #pragma unroll 2
    for (int s = 0; s < SPL; s++) {
        l += g_lp[(b * SPL + s) * NP + n];
        const u64* ap = (const u64*)(g_acc + ((b * SPL + s) * NP + n) * DI);
        #pragma unroll
        for (int i2 = 0; i2 < 16; i2++) y2[i2] = f2add(y2[i2], ap[i2]);
    }
    const float inv = 1.f / l;
    u64 inv2; asm("mov.b64 %0,{%1,%1};" : "=l"(inv2) : "f"(inv));
    #pragma unroll
    for (int i2 = 0; i2 < 16; i2++) {
        u64 z = 0ull;
        y2[i2] = f2fma(y2[i2], inv2, z);
    }

    const float* xb = x + b * CH * NP + n;
    float* ob = out + b * CH * NP + n;
    #pragma unroll 2
    for (int c = 0; c < CH; c++) {
        const u64* w2 = (const u64*)(ws + c * DI);
        u64 o2 = 0ull;
        #pragma unroll
        for (int i2 = 0; i2 < 16; i2++) o2 = f2fma(w2[i2], y2[i2], o2);
        ob[c * NP] = xb[c * NP] + f2hadd(o2);
    }
}

// ---------------------------------------------------------------------------
extern "C" void kernel_launch(void* const* d_in, const int* in_sizes, int n_in,
                              void* d_out, int out_size)
{
    const float* x       = (const float*)d_in[0];
    const float* gw      = (const float*)d_in[1];
    const float* theta_w = (const float*)d_in[2];
    const float* phi_w   = (const float*)d_in[3];
    const float* w_w     = (const float*)d_in[4];
    float* out           = (float*)d_out;

    void* pm = nullptr; cudaGetSymbolAddress(&pm, g_phimax);
    cudaMemsetAsync(pm, 0, sizeof(unsigned) * BATCH);
    void* pc = nullptr; cudaGetSymbolAddress(&pc, g_ctr);
    cudaMemsetAsync(pc, 0, sizeof(unsigned));

    static int cfg = 0;
    if (!cfg) {
        cudaFuncSetAttribute(attn_kernel, cudaFuncAttributeMaxDynamicSharedMemorySize, ASMEM);
        cfg = 1;
    }

    dim3 gp(NP / PQ, 3, BATCH);
    proj_kernel<<<gp, 128>>>(x, theta_w, phi_w, gw);

    attn_kernel<<<296, 256, ASMEM>>>();

    dim3 gm(NP / 128, BATCH);
    merge_kernel<<<gm, 128>>>(x, w_w, out);
}